// round 13
// baseline (speedup 1.0000x reference)
#include <cuda_runtime.h>
#include <math.h>
#include <cstdint>

#define NROW 4096          // 64*64 legality cells per board
#define QDIM 256           // quality vector length
#define NEG_FILL -1000000.0f
#define EOS_COEF 0.25f
#define ROWS_PB 2          // rows per block; 4 warps stream each row
#define MAXBLK 4096

// Per-block partials + ticket (static globals — no allocation)
__device__ float    g_lab[MAXBLK];
__device__ float    g_ce [MAXBLK];
__device__ float    g_mse[MAXBLK];
__device__ unsigned g_count;   // zero-init; last block resets to 0

// spread 8 bits to every 4th bit position (bit i -> bit 4i)
__device__ __forceinline__ unsigned spread4(unsigned x) {
    x = (x | (x << 12)) & 0x000F000Fu;
    x = (x | (x << 6))  & 0x03030303u;
    x = (x | (x << 3))  & 0x11111111u;
    return x;
}
__device__ __forceinline__ float warpSum(float v) {
    #pragma unroll
    for (int o = 16; o; o >>= 1) v += __shfl_xor_sync(0xffffffffu, v, o);
    return v;
}
__device__ __forceinline__ float warpMax(float v) {
    #pragma unroll
    for (int o = 16; o; o >>= 1) v = fmaxf(v, __shfl_xor_sync(0xffffffffu, v, o));
    return v;
}
__device__ __forceinline__ double blockReduceSumD(double v, double* shd) {
    int lane = threadIdx.x & 31, warp = threadIdx.x >> 5;
    #pragma unroll
    for (int o = 16; o; o >>= 1) v += __shfl_down_sync(0xffffffffu, v, o);
    if (lane == 0) shd[warp] = v;
    __syncthreads();
    if (warp == 0) {
        v = (lane < 8) ? shd[lane] : 0.0;
        #pragma unroll
        for (int o = 4; o; o >>= 1) v += __shfl_down_sync(0xffffffffu, v, o);
        if (lane == 0) shd[0] = v;
    }
    __syncthreads();
    double r = shd[0];
    __syncthreads();
    return r;
}

// One block = 2 rows, 8 warps. Phase 1: warp w streams quarter (w&3) of row
// (w>>2) — barrier-free, lane-coalesced. Phase 2: warps 0-1 run the 2 lineups.
__global__ __launch_bounds__(256, 8) void crit_kernel(
    const float* __restrict__ pl,     // pred_legal  [B,4096]
    const float* __restrict__ tl,     // target_legal[B,4096]
    const float4* __restrict__ pq4,   // pred_q      [B*64] float4
    const float4* __restrict__ tq4,   // target_q    [B*64] float4
    float* __restrict__ out, int B, int nblk)
{
    const int r0 = blockIdx.x * ROWS_PB;
    const int w = threadIdx.x >> 5, l = threadIdx.x & 31;
    const int t = threadIdx.x;

    __shared__ alignas(16) unsigned maskT[ROWS_PB * 128];   // 1 KB (ballot order)
    __shared__ alignas(16) unsigned maskP[ROWS_PB * 128];   // 1 KB
    __shared__ alignas(16) float pqs[ROWS_PB * QDIM];       // 2 KB
    __shared__ alignas(16) float tqs[ROWS_PB * QDIM];       // 2 KB
    __shared__ alignas(16) float lined[ROWS_PB * QDIM];     // 2 KB
    __shared__ unsigned char match[ROWS_PB * QDIM];         // 512 B
    __shared__ float rowCe[ROWS_PB], rowMse[ROWS_PB];
    __shared__ double shd[8];
    __shared__ unsigned lastFlag;

    // ---- stage quality vectors: 2 rows x 64 float4 per array ----
    if (t < 128) ((float4*)pqs)[t]       = __ldg(pq4 + (size_t)r0 * 64 + t);
    else         ((float4*)tqs)[t - 128] = __ldg(tq4 + (size_t)r0 * 64 + (t - 128));

    // ---- phase 1: warp w streams quarter (w&3) of row (w>>2): 1024 elements ----
    const int myRow = w >> 2;
    const int myQ   = w & 3;
    float accBce = 0.f;
    {
        const size_t off = (size_t)(r0 + myRow) * 1024 + myQ * 256;   // float4 units
        const float4* pl4 = (const float4*)pl + off;
        const float4* tl4 = (const float4*)tl + off;
        #pragma unroll
        for (int i = 0; i < 8; i++) {
            int idx = i * 32 + l;                       // lane-coalesced
            float4 pv = __ldg(pl4 + idx);
            float4 tv = __ldg(tl4 + idx);
            float px[4] = {pv.x, pv.y, pv.z, pv.w};
            float tx[4] = {tv.x, tv.y, tv.z, tv.w};
            bool pt[4], pp[4];
            #pragma unroll
            for (int j = 0; j < 4; j++) {
                float x = px[j], tg = tx[j];
                float sp  = __logf(1.f + __expf(-fabsf(x)));   // fast ok in BCE (R3)
                float bce = fmaxf(x, 0.f) - x * tg + sp;
                float wgt = fmaf(tg, 0.75f, 0.25f);            // tg in {0,1} exactly
                accBce = fmaf(wgt, bce, accBce);
                pt[j] = (tg == 1.f);
                pp[j] = (x  > 0.f);
            }
            unsigned bT0 = __ballot_sync(0xffffffffu, pt[0]);
            unsigned bT1 = __ballot_sync(0xffffffffu, pt[1]);
            unsigned bT2 = __ballot_sync(0xffffffffu, pt[2]);
            unsigned bT3 = __ballot_sync(0xffffffffu, pt[3]);
            unsigned bP0 = __ballot_sync(0xffffffffu, pp[0]);
            unsigned bP1 = __ballot_sync(0xffffffffu, pp[1]);
            unsigned bP2 = __ballot_sync(0xffffffffu, pp[2]);
            unsigned bP3 = __ballot_sync(0xffffffffu, pp[3]);
            // chunk c = myQ*8 + i of row myRow; word c*4+j, bit l = elt c*128+4l+j
            int base = myRow * 128 + (myQ * 8 + i) * 4;
            if (l < 4) {
                unsigned vT = (l == 0) ? bT0 : (l == 1) ? bT1 : (l == 2) ? bT2 : bT3;
                maskT[base + l] = vT;
            } else if (l < 8) {
                int j = l - 4;
                unsigned vP = (j == 0) ? bP0 : (j == 1) ? bP1 : (j == 2) ? bP2 : bP3;
                maskP[base + j] = vP;
            }
        }
    }
    __syncthreads();   // masks + staged quality vectors visible

    // ---- phase 2: warps 0-1 -> full lineup of row (r0 + w) ----
    if (w < ROWS_PB) {
        const float* pq = pqs + w * QDIM;
        const float* tq = tqs + w * QDIM;
        float* ln       = lined + w * QDIM;
        unsigned char* mt = match + w * QDIM;

        uint4 WT = ((const uint4*)(maskT + w * 128))[l];
        uint4 WP = ((const uint4*)(maskP + w * 128))[l];

        // STRIDED slot ownership: lane l owns slots {l, 32+l, ..., 224+l}.
        // Matches concentrate at low slot indices -> only j=0 (and rarely j=1)
        // has any active lane for the expf below.
        #pragma unroll
        for (int j = 0; j < 8; j++) {
            ln[j * 32 + l] = NEG_FILL;
            mt[j * 32 + l] = 0;
        }

        // transpose ballot-order -> row-major words
        unsigned mT[4], mP[4];
        #pragma unroll
        for (int k = 0; k < 4; k++) {
            unsigned sh = 8 * k;
            mT[k] = spread4((WT.x >> sh) & 0xFFu)
                  | (spread4((WT.y >> sh) & 0xFFu) << 1)
                  | (spread4((WT.z >> sh) & 0xFFu) << 2)
                  | (spread4((WT.w >> sh) & 0xFFu) << 3);
            mP[k] = spread4((WP.x >> sh) & 0xFFu)
                  | (spread4((WP.y >> sh) & 0xFFu) << 1)
                  | (spread4((WP.z >> sh) & 0xFFu) << 2)
                  | (spread4((WP.w >> sh) & 0xFFu) << 3);
        }

        int cT = 0, cP = 0;
        #pragma unroll
        for (int k = 0; k < 4; k++) { cT += __popc(mT[k]); cP += __popc(mP[k]); }
        int sTc = cT, sPc = cP;   // warp-inclusive scans
        #pragma unroll
        for (int o = 1; o < 32; o <<= 1) {
            int vT = __shfl_up_sync(0xffffffffu, sTc, o);
            int vP = __shfl_up_sync(0xffffffffu, sPc, o);
            if (l >= o) { sTc += vT; sPc += vP; }
        }
        int tIdx  = sTc - cT;
        int pBase = sPc - cP;
        __syncwarp();

        // sparse scatter (ranks unique -> plain stores)
        #pragma unroll
        for (int k = 0; k < 4; k++) {
            unsigned m = mT[k], p = mP[k];
            while (m) {
                int bit = __ffs(m) - 1;
                m &= m - 1;
                if ((p >> bit) & 1u) {
                    int pi = pBase + __popc(p & ((1u << bit) - 1u));
                    if (pi < QDIM - 1 && tIdx < QDIM - 1) {
                        ln[tIdx] = pq[pi];
                        mt[tIdx] = 1;
                    }
                }
                tIdx++;
            }
            pBase += __popc(p);
        }
        __syncwarp();

        // logsumexp over lined[0..254], sparse-exact:
        // exp(NEG_FILL - mx) is identical for every unmatched slot (0.0f when mx
        // is a real value by underflow; 1.0f when mx==NEG_FILL). Count them and
        // add n0*e0 — bit-identical to summing them individually.
        float vals[8];
        unsigned char mts[8];
        float mx = -INFINITY;
        #pragma unroll
        for (int j = 0; j < 8; j++) {
            vals[j] = ln[j * 32 + l];
            mts[j]  = mt[j * 32 + l];
            mx = fmaxf(mx, vals[j]);          // slot 255 is NEG_FILL: harmless
        }
        mx = warpMax(mx);
        float es = 0.f;
        int n0 = 0;
        #pragma unroll
        for (int j = 0; j < 8; j++) {
            if (j * 32 + l < QDIM - 1) {      // exclude slot 255
                if (mts[j]) es += expf(vals[j] - mx);   // PRECISE expf (CE x200)
                else        n0++;
            }
        }
        es += (float)n0 * expf(NEG_FILL - mx);
        es = warpSum(es);
        float lse = mx + logf(es);

        float wsum = 0.f, dot = 0.f;
        #pragma unroll
        for (int j = 0; j < 8; j++) {
            int idx = j * 32 + l;
            if (idx < QDIM - 1) {
                float wq = tq[idx] * (float)mts[j];
                wsum += wq;
                dot  += wq * (vals[j] - lse);
            }
        }
        wsum = warpSum(wsum);
        dot  = warpSum(dot);

        if (l == 0) {
            rowCe[w]  = -dot / (wsum + 1e-10f);
            float dq = pq[QDIM - 1] - tq[QDIM - 1];
            rowMse[w] = dq * dq;
        }
    }

    // ---- block reduce BCE (double) + per-block partials + ticket ----
    double sBce = blockReduceSumD((double)accBce, shd);

    if (t == 0) {
        float ce = 0.f, ms = 0.f;
        #pragma unroll
        for (int i = 0; i < ROWS_PB; i++) { ce += rowCe[i]; ms += rowMse[i]; }
        g_lab[blockIdx.x] = (float)sBce;
        g_ce [blockIdx.x] = ce;
        g_mse[blockIdx.x] = ms;
        __threadfence();
        unsigned old = atomicAdd(&g_count, 1u);
        lastFlag = (old == (unsigned)(nblk - 1)) ? 1u : 0u;
    }
    __syncthreads();

    // ---- last block: final scalar reduce ----
    if (lastFlag) {
        __threadfence();
        double sLab = 0.0, sCe = 0.0, sMse = 0.0;
        for (int i = t; i < nblk; i += 256) {
            sLab += (double)g_lab[i];
            sCe  += (double)g_ce[i];
            sMse += (double)g_mse[i];
        }
        sLab = blockReduceSumD(sLab, shd);
        sCe  = blockReduceSumD(sCe,  shd);
        sMse = blockReduceSumD(sMse, shd);
        if (t == 0) {
            double loss_labels = sLab / ((double)B * (double)NROW);
            double loss_ce     = sCe / (double)(QDIM - 1);
            double loss_mse    = sMse / (double)B;
            out[0] = (float)loss_labels;
            out[1] = (float)(loss_ce * 200.0 + loss_mse);
            g_count = 0;   // reset for next graph replay
        }
    }
}

extern "C" void kernel_launch(void* const* d_in, const int* in_sizes, int n_in,
                              void* d_out, int out_size) {
    const float* pred_legal   = (const float*)d_in[0];
    const float* pred_q       = (const float*)d_in[1];
    const float* target_legal = (const float*)d_in[2];
    const float* target_q     = (const float*)d_in[3];
    float* out = (float*)d_out;

    int B = in_sizes[1] / QDIM;      // 4096
    int nblk = B / ROWS_PB;          // 2048

    crit_kernel<<<nblk, 256>>>(pred_legal, target_legal,
                               (const float4*)pred_q,
                               (const float4*)target_q,
                               out, B, nblk);
}

// round 14
// speedup vs baseline: 1.1712x; 1.1712x over previous
#include <cuda_runtime.h>
#include <math.h>
#include <cstdint>

#define NROW 4096          // 64*64 legality cells per board
#define QDIM 256           // quality vector length
#define NEG_FILL -1000000.0f
#define EOS_COEF 0.25f
#define ROWS_PB 4          // rows per block; 2 warps stream each row
#define MAXBLK 4096

// Per-block partials + ticket (static globals — no allocation)
__device__ float    g_lab[MAXBLK];
__device__ float    g_ce [MAXBLK];
__device__ float    g_mse[MAXBLK];
__device__ unsigned g_count;   // zero-init; last block resets to 0

// spread 8 bits to every 4th bit position (bit i -> bit 4i)
__device__ __forceinline__ unsigned spread4(unsigned x) {
    x = (x | (x << 12)) & 0x000F000Fu;
    x = (x | (x << 6))  & 0x03030303u;
    x = (x | (x << 3))  & 0x11111111u;
    return x;
}
__device__ __forceinline__ float warpSum(float v) {
    #pragma unroll
    for (int o = 16; o; o >>= 1) v += __shfl_xor_sync(0xffffffffu, v, o);
    return v;
}
__device__ __forceinline__ float warpMax(float v) {
    #pragma unroll
    for (int o = 16; o; o >>= 1) v = fmaxf(v, __shfl_xor_sync(0xffffffffu, v, o));
    return v;
}
__device__ __forceinline__ double blockReduceSumD(double v, double* shd) {
    int lane = threadIdx.x & 31, warp = threadIdx.x >> 5;
    #pragma unroll
    for (int o = 16; o; o >>= 1) v += __shfl_down_sync(0xffffffffu, v, o);
    if (lane == 0) shd[warp] = v;
    __syncthreads();
    if (warp == 0) {
        v = (lane < 8) ? shd[lane] : 0.0;
        #pragma unroll
        for (int o = 4; o; o >>= 1) v += __shfl_down_sync(0xffffffffu, v, o);
        if (lane == 0) shd[0] = v;
    }
    __syncthreads();
    double r = shd[0];
    __syncthreads();
    return r;
}

// One block = 4 rows, 8 warps. Phase 1: warp w streams half (w&1) of row (w>>1)
// — barrier-free, lane-coalesced. Phase 2: warps 0-3 run the 4 lineups in parallel.
__global__ __launch_bounds__(256, 8) void crit_kernel(
    const float* __restrict__ pl,     // pred_legal  [B,4096]
    const float* __restrict__ tl,     // target_legal[B,4096]
    const float4* __restrict__ pq4,   // pred_q      [B*64] float4
    const float4* __restrict__ tq4,   // target_q    [B*64] float4
    float* __restrict__ out, int B, int nblk)
{
    const int r0 = blockIdx.x * ROWS_PB;
    const int w = threadIdx.x >> 5, l = threadIdx.x & 31;
    const int t = threadIdx.x;

    __shared__ alignas(16) unsigned maskT[ROWS_PB * 128];   // 2 KB (ballot order)
    __shared__ alignas(16) unsigned maskP[ROWS_PB * 128];   // 2 KB
    __shared__ alignas(16) float pqs[ROWS_PB * QDIM];       // 4 KB
    __shared__ alignas(16) float tqs[ROWS_PB * QDIM];       // 4 KB
    __shared__ alignas(16) float lined[ROWS_PB * QDIM];     // 4 KB
    __shared__ unsigned char match[ROWS_PB * QDIM];         // 1 KB
    __shared__ float rowCe[ROWS_PB], rowMse[ROWS_PB];
    __shared__ double shd[8];
    __shared__ unsigned lastFlag;

    // ---- stage quality vectors: 4 rows x 64 float4 = 256 float4, 1/thread ----
    {
        ((float4*)pqs)[t] = __ldg(pq4 + (size_t)r0 * 64 + t);
        ((float4*)tqs)[t] = __ldg(tq4 + (size_t)r0 * 64 + t);
    }

    // ---- phase 1: warp w streams half (w&1) of row (w>>1): 2048 elements ----
    const int myRow  = w >> 1;
    const int myHalf = w & 1;
    float accBce = 0.f;
    {
        const size_t rowOff = (size_t)(r0 + myRow) * 1024 + myHalf * 512; // float4
        const float4* pl4 = (const float4*)pl + rowOff;
        const float4* tl4 = (const float4*)tl + rowOff;
        #pragma unroll 4
        for (int i = 0; i < 16; i++) {
            int idx = i * 32 + l;                       // lane-coalesced
            float4 pv = __ldg(pl4 + idx);
            float4 tv = __ldg(tl4 + idx);
            float px[4] = {pv.x, pv.y, pv.z, pv.w};
            float tx[4] = {tv.x, tv.y, tv.z, tv.w};
            bool pt[4], pp[4];
            #pragma unroll
            for (int j = 0; j < 4; j++) {
                float x = px[j], tg = tx[j];
                float sp  = __logf(1.f + __expf(-fabsf(x)));   // fast ok in BCE (R3)
                float bce = fmaxf(x, 0.f) - x * tg + sp;
                float wgt = fmaf(tg, 0.75f, 0.25f);            // tg in {0,1} exactly
                accBce = fmaf(wgt, bce, accBce);
                pt[j] = (tg == 1.f);
                pp[j] = (x  > 0.f);
            }
            unsigned bT0 = __ballot_sync(0xffffffffu, pt[0]);
            unsigned bT1 = __ballot_sync(0xffffffffu, pt[1]);
            unsigned bT2 = __ballot_sync(0xffffffffu, pt[2]);
            unsigned bT3 = __ballot_sync(0xffffffffu, pt[3]);
            unsigned bP0 = __ballot_sync(0xffffffffu, pp[0]);
            unsigned bP1 = __ballot_sync(0xffffffffu, pp[1]);
            unsigned bP2 = __ballot_sync(0xffffffffu, pp[2]);
            unsigned bP3 = __ballot_sync(0xffffffffu, pp[3]);
            // chunk c = myHalf*16 + i of row myRow; word c*4+j, bit l
            int base = myRow * 128 + (myHalf * 16 + i) * 4;
            if (l < 4) {
                unsigned vT = (l == 0) ? bT0 : (l == 1) ? bT1 : (l == 2) ? bT2 : bT3;
                maskT[base + l] = vT;
            } else if (l < 8) {
                int j = l - 4;
                unsigned vP = (j == 0) ? bP0 : (j == 1) ? bP1 : (j == 2) ? bP2 : bP3;
                maskP[base + j] = vP;
            }
        }
    }
    __syncthreads();   // masks + staged quality vectors visible

    // ---- phase 2: warps 0-3 -> full lineup of row (r0 + w) ----
    if (w < ROWS_PB) {
        const float* pq = pqs + w * QDIM;
        const float* tq = tqs + w * QDIM;
        float* ln       = lined + w * QDIM;
        unsigned char* mt = match + w * QDIM;

        uint4 WT = ((const uint4*)(maskT + w * 128))[l];
        uint4 WP = ((const uint4*)(maskP + w * 128))[l];

        // STRIDED slot ownership: lane l owns slots {l, 32+l, ..., 224+l}.
        // Matches concentrate at low slot indices -> only j=0 (rarely j=1)
        // has active lanes for the expf below.
        #pragma unroll
        for (int j = 0; j < 8; j++) {
            ln[j * 32 + l] = NEG_FILL;
            mt[j * 32 + l] = 0;
        }

        // transpose ballot-order -> row-major words
        unsigned mT[4], mP[4];
        #pragma unroll
        for (int k = 0; k < 4; k++) {
            unsigned sh = 8 * k;
            mT[k] = spread4((WT.x >> sh) & 0xFFu)
                  | (spread4((WT.y >> sh) & 0xFFu) << 1)
                  | (spread4((WT.z >> sh) & 0xFFu) << 2)
                  | (spread4((WT.w >> sh) & 0xFFu) << 3);
            mP[k] = spread4((WP.x >> sh) & 0xFFu)
                  | (spread4((WP.y >> sh) & 0xFFu) << 1)
                  | (spread4((WP.z >> sh) & 0xFFu) << 2)
                  | (spread4((WP.w >> sh) & 0xFFu) << 3);
        }

        int cT = 0, cP = 0;
        #pragma unroll
        for (int k = 0; k < 4; k++) { cT += __popc(mT[k]); cP += __popc(mP[k]); }
        int sTc = cT, sPc = cP;   // warp-inclusive scans
        #pragma unroll
        for (int o = 1; o < 32; o <<= 1) {
            int vT = __shfl_up_sync(0xffffffffu, sTc, o);
            int vP = __shfl_up_sync(0xffffffffu, sPc, o);
            if (l >= o) { sTc += vT; sPc += vP; }
        }
        int tIdx  = sTc - cT;
        int pBase = sPc - cP;
        __syncwarp();

        // sparse scatter (ranks unique -> plain stores)
        #pragma unroll
        for (int k = 0; k < 4; k++) {
            unsigned m = mT[k], p = mP[k];
            while (m) {
                int bit = __ffs(m) - 1;
                m &= m - 1;
                if ((p >> bit) & 1u) {
                    int pi = pBase + __popc(p & ((1u << bit) - 1u));
                    if (pi < QDIM - 1 && tIdx < QDIM - 1) {
                        ln[tIdx] = pq[pi];
                        mt[tIdx] = 1;
                    }
                }
                tIdx++;
            }
            pBase += __popc(p);
        }
        __syncwarp();

        // logsumexp over lined[0..254], sparse-exact:
        // every unmatched slot contributes exp(NEG_FILL - mx), identical for all
        // of them (0.0f by underflow when mx is a real value; 1.0f when
        // mx==NEG_FILL). Count them and add n0*e0 — bit-identical to the ref.
        float vals[8];
        unsigned char mts[8];
        float mx = -INFINITY;
        #pragma unroll
        for (int j = 0; j < 8; j++) {
            vals[j] = ln[j * 32 + l];
            mts[j]  = mt[j * 32 + l];
            mx = fmaxf(mx, vals[j]);          // slot 255 is NEG_FILL: harmless
        }
        mx = warpMax(mx);
        float es = 0.f;
        int n0 = 0;
        #pragma unroll
        for (int j = 0; j < 8; j++) {
            if (j * 32 + l < QDIM - 1) {      // exclude slot 255
                if (mts[j]) es += expf(vals[j] - mx);   // PRECISE expf (CE x200)
                else        n0++;
            }
        }
        es += (float)n0 * expf(NEG_FILL - mx);
        es = warpSum(es);
        float lse = mx + logf(es);

        float wsum = 0.f, dot = 0.f;
        #pragma unroll
        for (int j = 0; j < 8; j++) {
            int idx = j * 32 + l;
            if (idx < QDIM - 1) {
                float wq = tq[idx] * (float)mts[j];
                wsum += wq;
                dot  += wq * (vals[j] - lse);
            }
        }
        wsum = warpSum(wsum);
        dot  = warpSum(dot);

        if (l == 0) {
            rowCe[w]  = -dot / (wsum + 1e-10f);
            float dq = pq[QDIM - 1] - tq[QDIM - 1];
            rowMse[w] = dq * dq;
        }
    }

    // ---- block reduce BCE (double) + per-block partials + ticket ----
    double sBce = blockReduceSumD((double)accBce, shd);

    if (t == 0) {
        float ce = 0.f, ms = 0.f;
        #pragma unroll
        for (int i = 0; i < ROWS_PB; i++) { ce += rowCe[i]; ms += rowMse[i]; }
        g_lab[blockIdx.x] = (float)sBce;
        g_ce [blockIdx.x] = ce;
        g_mse[blockIdx.x] = ms;
        __threadfence();
        unsigned old = atomicAdd(&g_count, 1u);
        lastFlag = (old == (unsigned)(nblk - 1)) ? 1u : 0u;
    }
    __syncthreads();

    // ---- last block: final scalar reduce ----
    if (lastFlag) {
        __threadfence();
        double sLab = 0.0, sCe = 0.0, sMse = 0.0;
        for (int i = t; i < nblk; i += 256) {
            sLab += (double)g_lab[i];
            sCe  += (double)g_ce[i];
            sMse += (double)g_mse[i];
        }
        sLab = blockReduceSumD(sLab, shd);
        sCe  = blockReduceSumD(sCe,  shd);
        sMse = blockReduceSumD(sMse, shd);
        if (t == 0) {
            double loss_labels = sLab / ((double)B * (double)NROW);
            double loss_ce     = sCe / (double)(QDIM - 1);
            double loss_mse    = sMse / (double)B;
            out[0] = (float)loss_labels;
            out[1] = (float)(loss_ce * 200.0 + loss_mse);
            g_count = 0;   // reset for next graph replay
        }
    }
}

extern "C" void kernel_launch(void* const* d_in, const int* in_sizes, int n_in,
                              void* d_out, int out_size) {
    const float* pred_legal   = (const float*)d_in[0];
    const float* pred_q       = (const float*)d_in[1];
    const float* target_legal = (const float*)d_in[2];
    const float* target_q     = (const float*)d_in[3];
    float* out = (float*)d_out;

    int B = in_sizes[1] / QDIM;      // 4096
    int nblk = B / ROWS_PB;          // 1024

    crit_kernel<<<nblk, 256>>>(pred_legal, target_legal,
                               (const float4*)pred_q,
                               (const float4*)target_q,
                               out, B, nblk);
}